// round 9
// baseline (speedup 1.0000x reference)
#include <cuda_runtime.h>

typedef unsigned long long u64;

#define NT 512
#define N_CHAIN 4
#define GRID_BLKS 132   // 4 chain + 128 conv

// ---- conv smem layout (floats) ----
#define C_W1S 0                        // 64 x 168
#define C_XS  10752                    // 3 x 8 x 72 = 1728
#define C_H0  12480                    // 64 x 132 = 8448
#define H0_LD 132
#define C_ADS 20928                    // 64 x 128 = 8192
#define C_SAS 29120                    // 64
#define C_B1S 29184                    // 64
#define SMEM_FLOATS 29248

// ---- device scratch ----
__device__ float g_M[4][4096];   // chain matrix slots, row-major [r*64+c]
__device__ float g_sv[4][64];    // matching s-vectors
__device__ float g_AD[8192];     // published A = W2^200, dup layout [c][2*o]
__device__ float g_sA[64];
__device__ int   g_bar[32];      // [0]; own 128B line — chain blocks only
__device__ int   g_flag[32];     // [0]; own 128B line — conv blocks only
__device__ int   g_done[32];     // [0]; own 128B line

__device__ __forceinline__ u64 pk2(float a, float b) {
    u64 r; asm("mov.b64 %0, {%1, %2};" : "=l"(r) : "f"(a), "f"(b)); return r;
}
__device__ __forceinline__ float2 up2(u64 v) {
    float2 r; asm("mov.b64 {%0, %1}, %2;" : "=f"(r.x), "=f"(r.y) : "l"(v)); return r;
}
__device__ __forceinline__ void fma2(u64& d, u64 a, u64 b) {
    asm("fma.rn.f32x2 %0, %1, %2, %0;" : "+l"(d) : "l"(a), "l"(b));
}
__device__ __forceinline__ void fadd2(u64& d, u64 a) {
    asm("add.rn.f32x2 %0, %0, %1;" : "+l"(d) : "l"(a));
}

__global__ void __launch_bounds__(NT, 1)
fused(const float* __restrict__ x, const float* __restrict__ W1,
      const float* __restrict__ b1, const float* __restrict__ W2,
      const float* __restrict__ b2, float* __restrict__ out)
{
    extern __shared__ float sm[];
    const int t   = threadIdx.x;
    const int bid = blockIdx.x;

    if (bid < N_CHAIN) {
        // ================= chain blocks: 4 blocks x 16 rows =================
        float* Bs  = sm;           // 64 x 66
        float* As  = sm + 4224;    // 16 x 64
        float* scr = sm + 5248;    // 256 x 16B merge scratch
        float* sAs = sm + 9344;    // 64
        float* sBs = sm + 9408;    // 64

        // addition chain: 2,4,8,16,24(16+8),25(24+1),50,100,200 ; slot -1 = (W2,b2)
        const signed char A_[9] = {-1, 0, 1, 2, 3, 1, 3, 1, 3};
        const signed char B_[9] = {-1, 0, 1, 2, 2,-1, 3, 1, 3};
        const signed char C_[9] = { 0, 1, 2, 3, 1, 3, 1, 3, 0};  // [8]: publish

        const int kh = t >> 8;          // k half: 0/1
        const int rp = (t >> 5) & 7;    // row pair 0..7
        const int cp = t & 31;          // col pair 0..31
        const int c0 = 2 * cp;
        const int mergeIdx = rp * 32 + cp;

#pragma unroll 1
        for (int s = 0; s < 9; ++s) {
            if (s > 0) {
                if (t == 0) {
                    while (atomicAdd(&g_bar[0], 0) < N_CHAIN * s) __nanosleep(32);
                }
                __syncthreads();
            }
            const int ai = A_[s], bi = B_[s];
            const float* Ap  = (ai < 0) ? W2 : g_M[ai];
            const float* Bp  = (bi < 0) ? W2 : g_M[bi];
            const float* sAp = (ai < 0) ? b2 : g_sv[ai];
            const float* sBp = (bi < 0) ? b2 : g_sv[bi];

            // stage loads: full B (stride 66), this block's 16 A rows, s-vectors
            for (int i = t; i < 4096; i += NT)
                Bs[(i >> 6) * 66 + (i & 63)] = __ldcg(Bp + i);
            for (int i = t; i < 1024; i += NT)
                As[i] = __ldcg(Ap + bid * 1024 + i);
            if (t < 64) {
                sAs[t] = __ldcg(sAp + t);
                sBs[t] = __ldcg(sBp + t);
            }
            __syncthreads();

            // C[r][c0..c0+1] = sum_k A[r][k] * B[k][c0..c0+1], k-split by kh
            const float* ar0 = As + (rp * 2) * 64 + kh * 32;
            const float* ar1 = ar0 + 64;
            const float* bp  = Bs + (kh * 32) * 66 + c0;
            u64 acc0 = 0, acc1 = 0;
#pragma unroll 8
            for (int k = 0; k < 32; ++k) {
                float a0 = ar0[k], a1 = ar1[k];
                u64 bv = *(const u64*)bp;
                fma2(acc0, pk2(a0, a0), bv);
                fma2(acc1, pk2(a1, a1), bv);
                bp += 66;
            }

            if (kh == 1) {
                ulonglong2 v; v.x = acc0; v.y = acc1;
                *(ulonglong2*)(scr + mergeIdx * 4) = v;
            }
            __syncthreads();
            if (kh == 0) {
                ulonglong2 p = *(const ulonglong2*)(scr + mergeIdx * 4);
                fadd2(acc0, p.x);
                fadd2(acc1, p.y);
                const int r0 = bid * 16 + rp * 2, r1 = r0 + 1;
                float2 v0 = up2(acc0), v1 = up2(acc1);
                if (s < 8) {
                    __stcg((float2*)(g_M[C_[s]] + r0 * 64 + c0), v0);
                    __stcg((float2*)(g_M[C_[s]] + r1 * 64 + c0), v1);
                } else {
                    // publish dup layout g_AD[c][2o], g_AD[c][2o+1] = A[o][c]
                    __stcg((float2*)(g_AD + (c0)     * 128 + 2 * r0), make_float2(v0.x, v0.x));
                    __stcg((float2*)(g_AD + (c0 + 1) * 128 + 2 * r0), make_float2(v0.y, v0.y));
                    __stcg((float2*)(g_AD + (c0)     * 128 + 2 * r1), make_float2(v1.x, v1.x));
                    __stcg((float2*)(g_AD + (c0 + 1) * 128 + 2 * r1), make_float2(v1.y, v1.y));
                }
            }
            // s' = P_B * s_A + s_B  (powers of one map commute)
            if (bid == 0 && t < 64) {
                float ss = sBs[t];
#pragma unroll 8
                for (int k = 0; k < 64; ++k)
                    ss = fmaf(Bs[t * 66 + k], sAs[k], ss);
                if (s < 8) __stcg(g_sv[C_[s]] + t, ss);
                else       __stcg(g_sA + t, ss);
            }
            __threadfence();
            __syncthreads();
            if (t == 0) {
                int old = atomicAdd(&g_bar[0], 1);
                if (s == 8 && old == 9 * N_CHAIN - 1) {
                    __threadfence();
                    atomicExch(&g_flag[0], 1);   // release: all publishes visible
                }
            }
        }
    } else {
        // ================= conv + apply blocks =================
        float* W1s = sm + C_W1S;
        float* xs  = sm + C_XS;
        float* h0  = sm + C_H0;
        float* ADs = sm + C_ADS;
        float* sAs = sm + C_SAS;
        float* b1s = sm + C_B1S;

        const int r0 = (bid - N_CHAIN) * 2;
        const int bb = r0 >> 6, y0 = r0 & 63;   // both rows in same image

        for (int i = t; i < 10752; i += NT) {
            int m = i / 168, jp = i % 168;
            int ii = jp / 56, r = jp % 56, ky = r / 8, kx = r % 8;
            W1s[i] = (kx < 7) ? W1[m * 147 + ii * 49 + ky * 7 + kx] : 0.0f;
        }
        if (t < 64) b1s[t] = b1[t];
        for (int i = t; i < 1728; i += NT) {
            int ii = i / 576, rem = i % 576;
            int yy = rem / 72, xx = rem % 72;
            xs[i] = (xx < 70) ? x[((bb * 3 + ii) * 70 + (y0 + yy)) * 70 + xx] : 0.0f;
        }
        __syncthreads();

        // ---- conv: h0 = conv7x7(x, W1) + b1, 2 rows paired in f32x2 ----
        const int xq = t & 7, oc = t >> 3;
        const int x0 = xq * 8;

        u64 acc[8];
        {
            u64 bv = pk2(b1s[oc], b1s[oc]);
#pragma unroll
            for (int xi = 0; xi < 8; ++xi) acc[xi] = bv;
        }

#pragma unroll 1
        for (int ii = 0; ii < 3; ++ii) {
#pragma unroll 1
            for (int ky = 0; ky < 7; ++ky) {
                const float* p0 = xs + (ii * 8 + ky) * 72 + x0;
                const float* p1 = p0 + 72;
                float a0[16], a1[16];
#pragma unroll
                for (int q = 0; q < 4; ++q) {
                    float4 u = *(const float4*)(p0 + q * 4);
                    a0[q*4+0] = u.x; a0[q*4+1] = u.y; a0[q*4+2] = u.z; a0[q*4+3] = u.w;
                    float4 v = *(const float4*)(p1 + q * 4);
                    a1[q*4+0] = v.x; a1[q*4+1] = v.y; a1[q*4+2] = v.z; a1[q*4+3] = v.w;
                }
                u64 xwp[14];
#pragma unroll
                for (int i = 0; i < 14; ++i) xwp[i] = pk2(a0[i], a1[i]);

                const float* wq = W1s + oc * 168 + ii * 56 + ky * 8;
                float4 w0 = *(const float4*)(wq);
                float4 w1 = *(const float4*)(wq + 4);
                u64 wp[7];
                wp[0] = pk2(w0.x, w0.x); wp[1] = pk2(w0.y, w0.y);
                wp[2] = pk2(w0.z, w0.z); wp[3] = pk2(w0.w, w0.w);
                wp[4] = pk2(w1.x, w1.x); wp[5] = pk2(w1.y, w1.y);
                wp[6] = pk2(w1.z, w1.z);
#pragma unroll
                for (int kx = 0; kx < 7; ++kx)
#pragma unroll
                    for (int xi = 0; xi < 8; ++xi)
                        fma2(acc[xi], wp[kx], xwp[kx + xi]);
            }
        }

        // ---- h0 -> smem [c][px], px = row*64 + x ----
        {
            float2 v[8];
#pragma unroll
            for (int xi = 0; xi < 8; ++xi) v[xi] = up2(acc[xi]);
            float* hb = h0 + oc * H0_LD;
            *(float4*)(hb + x0)          = make_float4(v[0].x, v[1].x, v[2].x, v[3].x);
            *(float4*)(hb + x0 + 4)      = make_float4(v[4].x, v[5].x, v[6].x, v[7].x);
            *(float4*)(hb + 64 + x0)     = make_float4(v[0].y, v[1].y, v[2].y, v[3].y);
            *(float4*)(hb + 64 + x0 + 4) = make_float4(v[4].y, v[5].y, v[6].y, v[7].y);
        }
        __syncthreads();

        // ---- wait for chain: poll the dedicated flag line only ----
        if (t == 0) {
            while (atomicAdd(&g_flag[0], 0) == 0) __nanosleep(256);
        }
        __syncthreads();
        for (int i = t; i < 8192; i += NT) ADs[i] = __ldcg(&g_AD[i]);
        if (t < 64) sAs[t] = __ldcg(&g_sA[t]);
        __syncthreads();

        // ---- apply: out = A*h0 + sA  (2 oc x 8 px per thread) ----
        const int po = t >> 4, pq = t & 15;
        const int o0 = po * 2, px0 = pq * 8;

        u64 ap[2][4] = {};
#pragma unroll 4
        for (int c = 0; c < 64; ++c) {
            ulonglong2 ad  = *(const ulonglong2*)(ADs + c * 128 + 4 * po);
            ulonglong2 hv0 = *(const ulonglong2*)(h0 + c * H0_LD + px0);
            ulonglong2 hv1 = *(const ulonglong2*)(h0 + c * H0_LD + px0 + 4);
            fma2(ap[0][0], ad.x, hv0.x); fma2(ap[0][1], ad.x, hv0.y);
            fma2(ap[0][2], ad.x, hv1.x); fma2(ap[0][3], ad.x, hv1.y);
            fma2(ap[1][0], ad.y, hv0.x); fma2(ap[1][1], ad.y, hv0.y);
            fma2(ap[1][2], ad.y, hv1.x); fma2(ap[1][3], ad.y, hv1.y);
        }

        const int rr = px0 >> 6, xx0 = px0 & 63, yy = y0 + rr;
#pragma unroll
        for (int j = 0; j < 2; ++j) {
            int o = o0 + j;
            float sa = sAs[o];
            float2 v0 = up2(ap[j][0]), v1 = up2(ap[j][1]);
            float2 v2 = up2(ap[j][2]), v3 = up2(ap[j][3]);
            float* pd = out + ((bb * 64 + o) * 64 + yy) * 64 + xx0;
            *(float4*)(pd)     = make_float4(v0.x + sa, v0.y + sa, v1.x + sa, v1.y + sa);
            *(float4*)(pd + 4) = make_float4(v2.x + sa, v2.y + sa, v3.x + sa, v3.y + sa);
        }
    }

    // ---- self-resetting counters so graph replays start clean ----
    __syncthreads();
    if (t == 0) {
        __threadfence();
        int d = atomicAdd(&g_done[0], 1);
        if (d == GRID_BLKS - 1) {
            atomicExch(&g_bar[0], 0);
            atomicExch(&g_flag[0], 0);
            atomicExch(&g_done[0], 0);
        }
    }
}

extern "C" void kernel_launch(void* const* d_in, const int* in_sizes, int n_in,
                              void* d_out, int out_size)
{
    (void)in_sizes; (void)n_in; (void)out_size;
    const float* x  = (const float*)d_in[0];
    const float* W1 = (const float*)d_in[1];
    const float* b1 = (const float*)d_in[2];
    const float* W2 = (const float*)d_in[3];
    const float* b2 = (const float*)d_in[4];
    float* out = (float*)d_out;

    const size_t smem = (size_t)SMEM_FLOATS * sizeof(float);
    cudaFuncSetAttribute(fused, cudaFuncAttributeMaxDynamicSharedMemorySize, (int)smem);
    fused<<<GRID_BLKS, NT, smem>>>(x, W1, b1, W2, b2, out);
}